// round 1
// baseline (speedup 1.0000x reference)
#include <cuda_runtime.h>

#define LSEQ 65536
#define NB 32
#define NC 16
#define KW 8
#define THRV 0.25f
#define BETA 15.0f
#define XSC 20.0f

__device__ __forceinline__ float softplusf(float x) {
    return (x > 0.f) ? (x + log1pf(expf(-x))) : log1pf(expf(x));
}

// One-warp blocks. Block = (seq, quarter): seq in [0,512) = b*16+c, quarter in [0,4).
// Lane owns a 512-step chunk: chunk start p0 = (quarter*32 + lane)*512.
// 64-step warmup from v=0 (exact for p0==0; spike resets make it bit-converge otherwise).
// 16 phases of 32 steps: compute into shared tiles, drain coalesced.
__global__ __launch_bounds__(32) void snn_main(
    const float* __restrict__ x,
    const float* __restrict__ wa, const float* __restrict__ wb,
    const float* __restrict__ rta, const float* __restrict__ rtb,
    const float* __restrict__ rga, const float* __restrict__ rgb,
    float* __restrict__ outI, float* __restrict__ outZ, float* __restrict__ outS)
{
    __shared__ float tI[32][33];
    __shared__ float tZ[32][33];
    __shared__ unsigned sM[32];

    const int bid = blockIdx.x;
    const int seq = bid >> 2;       // 0..511
    const int quarter = bid & 3;
    const int lane = threadIdx.x;
    const int b = seq >> 4;
    const int c = seq & 15;
    const int fidx = c & 7;
    const int isB = (c >> 3) & 1;

    const float* wrow = (isB ? wb : wa) + fidx * KW;
    const float rt = (isB ? rtb : rta)[fidx];
    const float rg = (isB ? rgb : rga)[0];

    float wloc[KW];
    float nsq = 0.f;
#pragma unroll
    for (int k = 0; k < KW; k++) { wloc[k] = wrow[k]; nsq = fmaf(wloc[k], wloc[k], nsq); }
    float norm = sqrtf(nsq);
    if (norm < 1e-8f) norm = 1e-8f;
    const float g = softplusf(rg) + 1e-4f;
    const float scale = g * XSC / norm;   // GAIN = 1
    float we[KW];
#pragma unroll
    for (int k = 0; k < KW; k++) we[k] = wloc[k] * scale;

    const float alpha = expf(-1.0f / (softplusf(rt) + 1e-4f));
    const float oma = 1.0f - alpha;
    const float nBT = -BETA * THRV;

    const float* xr = x + ((size_t)(b * 2 + isB) << 16);
    const int p0 = (quarter * 32 + lane) * 512;
    const int warm = (p0 == 0) ? 0 : 64;
    int lcur = p0 - warm;

    // sliding window: xw[0..7] = x[l-8 .. l-1]
    float xw[12];
    if (lcur >= 8) {
        float4 a4 = *(const float4*)(xr + lcur - 8);
        float4 b4 = *(const float4*)(xr + lcur - 4);
        xw[0] = a4.x; xw[1] = a4.y; xw[2] = a4.z; xw[3] = a4.w;
        xw[4] = b4.x; xw[5] = b4.y; xw[6] = b4.z; xw[7] = b4.w;
    } else {
#pragma unroll
        for (int k = 0; k < 8; k++) xw[k] = 0.f;
    }

    float v = 0.f;

    // ---- warmup (0 or 64 steps), no emission ----
    for (int gg = 0; gg < (warm >> 2); ++gg) {
        float4 xv = *(const float4*)(xr + lcur);
        xw[8] = xv.x; xw[9] = xv.y; xw[10] = xv.z; xw[11] = xv.w;
#pragma unroll
        for (int k = 0; k < 4; k++) {
            float I = 0.f;
#pragma unroll
            for (int j = 0; j < 8; j++) I = fmaf(we[j], xw[k + 1 + j], I);
            float vpre = fmaf(alpha, v, oma * I);
            v = (vpre >= THRV) ? 0.f : vpre;
        }
#pragma unroll
        for (int j = 0; j < 8; j++) xw[j] = xw[j + 4];
        lcur += 4;
    }

    // ---- main: 16 phases of 32 steps ----
    const size_t seqoff = (size_t)seq << 16;
    for (int ph = 0; ph < 16; ++ph) {
        // prefetch all 8 group loads for this phase (MLP=8)
        float4 xq[8];
#pragma unroll
        for (int gg = 0; gg < 8; gg++) xq[gg] = *(const float4*)(xr + lcur + gg * 4);

        unsigned smask = 0u;
#pragma unroll
        for (int gg = 0; gg < 8; gg++) {
            float4 xv = xq[gg];
            xw[8] = xv.x; xw[9] = xv.y; xw[10] = xv.z; xw[11] = xv.w;
#pragma unroll
            for (int k = 0; k < 4; k++) {
                const int idx = gg * 4 + k;
                float I = 0.f;
#pragma unroll
                for (int j = 0; j < 8; j++) I = fmaf(we[j], xw[k + 1 + j], I);
                float vpre = fmaf(alpha, v, oma * I);
                tI[lane][idx] = I;
                tZ[lane][idx] = fmaf(BETA, vpre, nBT);
                bool sp = (vpre >= THRV);
                smask |= (sp ? 1u : 0u) << idx;
                v = sp ? 0.f : vpre;
            }
#pragma unroll
            for (int j = 0; j < 8; j++) xw[j] = xw[j + 4];
        }
        lcur += 32;
        sM[lane] = smask;
        __syncwarp();

        // drain: row j = lane-j's chunk, 32 contiguous floats -> coalesced 128B stores
        const size_t base = seqoff + (size_t)((quarter * 32) * 512) + (size_t)(ph * 32 + lane);
#pragma unroll 8
        for (int j = 0; j < 32; ++j) {
            size_t gidx = base + (size_t)j * 512;
            float vi = tI[j][lane];
            float vz = tZ[j][lane];
            float vs = (float)((sM[j] >> lane) & 1u);
            outI[gidx] = vi;
            outZ[gidx] = vz;
            outS[gidx] = vs;
        }
        __syncwarp();
    }
}

// logits[b,l] = max_c z[b,c,l]; float4 over l, coalesced.
__global__ __launch_bounds__(256) void logits_kernel(
    const float* __restrict__ z, float* __restrict__ out)
{
    int idx = blockIdx.x * blockDim.x + threadIdx.x;  // B*L/4 = 524288
    int b = idx >> 14;            // L/4 = 16384
    int l4 = idx & 16383;
    const float4* zp = (const float4*)z + ((size_t)b << 18) + l4;  // b*16*L/4
    float4 m = zp[0];
#pragma unroll
    for (int cc = 1; cc < 16; ++cc) {
        float4 t = zp[(size_t)cc << 14];
        m.x = fmaxf(m.x, t.x); m.y = fmaxf(m.y, t.y);
        m.z = fmaxf(m.z, t.z); m.w = fmaxf(m.w, t.w);
    }
    ((float4*)out)[idx] = m;
}

extern "C" void kernel_launch(void* const* d_in, const int* in_sizes, int n_in,
                              void* d_out, int out_size)
{
    const float* x   = (const float*)d_in[0];
    const float* wa  = (const float*)d_in[1];
    const float* wb  = (const float*)d_in[2];
    const float* rta = (const float*)d_in[3];
    const float* rtb = (const float*)d_in[4];
    const float* rga = (const float*)d_in[5];
    const float* rgb = (const float*)d_in[6];

    float* out = (float*)d_out;
    const size_t plane = (size_t)NB * NC * LSEQ;   // 33554432
    float* outI = out;
    float* outZ = out + plane;
    float* outS = out + 2 * plane;
    float* outL = out + 3 * plane;

    snn_main<<<2048, 32>>>(x, wa, wb, rta, rtb, rga, rgb, outI, outZ, outS);
    logits_kernel<<<2048, 256>>>(outZ, outL);
}

// round 2
// speedup vs baseline: 1.1457x; 1.1457x over previous
#include <cuda_runtime.h>

#define LSEQ 65536
#define NB 32
#define NC 16
#define KW 8
#define THRV 0.25f
#define BETA 15.0f
#define XSC 20.0f

#define TILE_STRIDE 33            // 32 steps + 1 pad (bank-conflict-free both ways)
#define WARP_TILE (32 * TILE_STRIDE)   // 1056 floats per warp tile
#define SMEM_FLOATS (2 * 16 * WARP_TILE + 512)   // tI + tZ + masks
#define SMEM_BYTES (SMEM_FLOATS * 4)             // 137216

__device__ __forceinline__ float softplusf(float x) {
    return (x > 0.f) ? (x + log1pf(expf(-x))) : log1pf(expf(x));
}

// 128 blocks x 512 threads. block = (b, quarter), warp w = channel c, lane owns a
// 512-step chunk starting at (quarter*32+lane)*512 with a 64-step warmup from v=0
// (exact for chunk 0; spike-resets make it bit-converge otherwise).
// 16 phases of 32 steps: compute into per-warp shared tiles, drain coalesced
// float4 streaming stores; logits = max over the 16 warps' z tiles (fused).
__global__ __launch_bounds__(512, 1) void snn_fused(
    const float* __restrict__ x,
    const float* __restrict__ wa, const float* __restrict__ wb,
    const float* __restrict__ rta, const float* __restrict__ rtb,
    const float* __restrict__ rga, const float* __restrict__ rgb,
    float* __restrict__ outI, float* __restrict__ outZ,
    float* __restrict__ outS, float* __restrict__ outL)
{
    extern __shared__ float smem[];
    float* tI = smem;                          // [16][32][33]
    float* tZ = smem + 16 * WARP_TILE;         // [16][32][33]
    unsigned* sM = (unsigned*)(smem + 32 * WARP_TILE);  // [16][32]

    const int b = blockIdx.x >> 2;
    const int quarter = blockIdx.x & 3;
    const int w = threadIdx.x >> 5;            // channel c = w, 0..15
    const int lane = threadIdx.x & 31;
    const int fidx = w & 7;
    const int isB = w >> 3;

    const float* wrow = (isB ? wb : wa) + fidx * KW;
    const float rt = (isB ? rtb : rta)[fidx];
    const float rg = (isB ? rgb : rga)[0];

    float wloc[KW];
    float nsq = 0.f;
#pragma unroll
    for (int k = 0; k < KW; k++) { wloc[k] = wrow[k]; nsq = fmaf(wloc[k], wloc[k], nsq); }
    float norm = sqrtf(nsq);
    if (norm < 1e-8f) norm = 1e-8f;
    const float g = softplusf(rg) + 1e-4f;
    const float scale = g * XSC / norm;        // GAIN = 1
    float we[KW];
#pragma unroll
    for (int k = 0; k < KW; k++) we[k] = wloc[k] * scale;

    const float alpha = expf(-1.0f / (softplusf(rt) + 1e-4f));
    const float oma = 1.0f - alpha;
    const float nBT = -BETA * THRV;

    const float* xr = x + ((size_t)(b * 2 + isB) << 16);
    const int p0 = (quarter * 32 + lane) * 512;
    const int warm = (p0 == 0) ? 0 : 64;
    int lcur = p0 - warm;

    // sliding window: xw[0..7] = x[l-8 .. l-1]
    float xw[12];
    if (lcur >= 8) {
        float4 a4 = *(const float4*)(xr + lcur - 8);
        float4 b4 = *(const float4*)(xr + lcur - 4);
        xw[0] = a4.x; xw[1] = a4.y; xw[2] = a4.z; xw[3] = a4.w;
        xw[4] = b4.x; xw[5] = b4.y; xw[6] = b4.z; xw[7] = b4.w;
    } else {
#pragma unroll
        for (int k = 0; k < 8; k++) xw[k] = 0.f;
    }

    float v = 0.f;

    // ---- warmup (0 or 64 steps), no emission ----
    for (int gg = 0; gg < (warm >> 2); ++gg) {
        float4 xv = *(const float4*)(xr + lcur);
        xw[8] = xv.x; xw[9] = xv.y; xw[10] = xv.z; xw[11] = xv.w;
#pragma unroll
        for (int k = 0; k < 4; k++) {
            float I = 0.f;
#pragma unroll
            for (int j = 0; j < 8; j++) I = fmaf(we[j], xw[k + 1 + j], I);
            float vpre = fmaf(alpha, v, oma * I);
            v = (vpre >= THRV) ? 0.f : vpre;
        }
#pragma unroll
        for (int j = 0; j < 8; j++) xw[j] = xw[j + 4];
        lcur += 4;
    }

    float* mtI = tI + w * WARP_TILE;
    float* mtZ = tZ + w * WARP_TILE;
    unsigned* mM = sM + w * 32;

    const size_t seqoff = ((size_t)(b * NC + w)) << 16;
    const int rsub = lane >> 3;          // 0..3
    const int cq = (lane & 7) * 4;       // 0,4,...,28

    for (int ph = 0; ph < 16; ++ph) {
        // prefetch all 8 group loads for this phase (MLP=8)
        float4 xq[8];
#pragma unroll
        for (int gg = 0; gg < 8; gg++) xq[gg] = *(const float4*)(xr + lcur + gg * 4);

        unsigned smask = 0u;
        float* rowI = mtI + lane * TILE_STRIDE;
        float* rowZ = mtZ + lane * TILE_STRIDE;
#pragma unroll
        for (int gg = 0; gg < 8; gg++) {
            float4 xv = xq[gg];
            xw[8] = xv.x; xw[9] = xv.y; xw[10] = xv.z; xw[11] = xv.w;
#pragma unroll
            for (int k = 0; k < 4; k++) {
                const int idx = gg * 4 + k;
                float I = 0.f;
#pragma unroll
                for (int j = 0; j < 8; j++) I = fmaf(we[j], xw[k + 1 + j], I);
                float vpre = fmaf(alpha, v, oma * I);
                rowI[idx] = I;
                rowZ[idx] = fmaf(BETA, vpre, nBT);
                bool sp = (vpre >= THRV);
                smask |= (sp ? 1u : 0u) << idx;
                v = sp ? 0.f : vpre;
            }
#pragma unroll
            for (int j = 0; j < 8; j++) xw[j] = xw[j + 4];
        }
        lcur += 32;
        mM[lane] = smask;
        __syncthreads();

        // ---- drain I/Z/S: per-warp tile -> coalesced float4 streaming stores ----
        const size_t lbase = (size_t)quarter * 16384 + (size_t)(ph * 32);
#pragma unroll
        for (int it = 0; it < 8; ++it) {
            const int r = it * 4 + rsub;                  // chunk row 0..31
            const size_t gi = seqoff + lbase + (size_t)r * 512 + cq;
            const float* pI = mtI + r * TILE_STRIDE + cq;
            const float* pZ = mtZ + r * TILE_STRIDE + cq;
            float4 vi = make_float4(pI[0], pI[1], pI[2], pI[3]);
            float4 vz = make_float4(pZ[0], pZ[1], pZ[2], pZ[3]);
            unsigned mm = mM[r] >> cq;
            float4 vs = make_float4((float)(mm & 1u), (float)((mm >> 1) & 1u),
                                    (float)((mm >> 2) & 1u), (float)((mm >> 3) & 1u));
            __stcs((float4*)(outI + gi), vi);
            __stcs((float4*)(outZ + gi), vz);
            __stcs((float4*)(outS + gi), vs);
        }

        // ---- fused logits: max over 16 channels of z, from smem ----
        const int t = threadIdx.x;
        if (t < 256) {
            const int j = t >> 3;             // chunk row 0..31
            const int q = (t & 7) * 4;        // step quad
            const float* p = tZ + j * TILE_STRIDE + q;
            float4 m4 = make_float4(p[0], p[1], p[2], p[3]);
#pragma unroll
            for (int w2 = 1; w2 < 16; ++w2) {
                p += WARP_TILE;
                m4.x = fmaxf(m4.x, p[0]); m4.y = fmaxf(m4.y, p[1]);
                m4.z = fmaxf(m4.z, p[2]); m4.w = fmaxf(m4.w, p[3]);
            }
            const size_t gl = (((size_t)b) << 16) + lbase + (size_t)j * 512 + q;
            __stcs((float4*)(outL + gl), m4);
        }
        __syncthreads();
    }
}

extern "C" void kernel_launch(void* const* d_in, const int* in_sizes, int n_in,
                              void* d_out, int out_size)
{
    const float* x   = (const float*)d_in[0];
    const float* wa  = (const float*)d_in[1];
    const float* wb  = (const float*)d_in[2];
    const float* rta = (const float*)d_in[3];
    const float* rtb = (const float*)d_in[4];
    const float* rga = (const float*)d_in[5];
    const float* rgb = (const float*)d_in[6];

    float* out = (float*)d_out;
    const size_t plane = (size_t)NB * NC * LSEQ;   // 33554432
    float* outI = out;
    float* outZ = out + plane;
    float* outS = out + 2 * plane;
    float* outL = out + 3 * plane;

    cudaFuncSetAttribute(snn_fused, cudaFuncAttributeMaxDynamicSharedMemorySize, SMEM_BYTES);
    snn_fused<<<128, 512, SMEM_BYTES>>>(x, wa, wb, rta, rtb, rga, rgb,
                                        outI, outZ, outS, outL);
}

// round 5
// speedup vs baseline: 1.1638x; 1.0158x over previous
#include <cuda_runtime.h>

#define LSEQ 65536
#define NB 32
#define NC 16
#define KW 8
#define THRV 0.25f
#define BETA 15.0f
#define XSC 20.0f

#define TILE_STRIDE 33                 // 32 steps + carry slot (col 32)
#define WARP_TILE (32 * TILE_STRIDE)   // per-warp z tile, 1056 floats
#define SMEM_FLOATS (32 * WARP_TILE + 32 * 32)   // tZ[32 warps] + masks
#define SMEM_BYTES (SMEM_FLOATS * 4)             // 139264

__device__ __forceinline__ float softplusf(float x) {
    return (x > 0.f) ? (x + log1pf(expf(-x))) : log1pf(expf(x));
}

// 128 blocks x 1024 threads (32 warps). block=(b,quarter); warp w: channel c=w>>1,
// half h=w&1. Lane owns a 256-step chunk at quarter*16384 + h*8192 + lane*256,
// warmed up 64 steps from v=0 (exact: spike resets re-synchronize trajectories).
// 8 phases x 32 steps. Only z is staged in smem; I is reconstructed in the drain:
//   vpre = z/BETA + THR ; v_prev = vpre_prev*(1-s_prev) ; I = (vpre - a*v_prev)/(1-a)
// Carry v (post-reset, phase entry) lives in tile col 32. Logits fused from smem.
__global__ __launch_bounds__(1024, 1) void snn_fused(
    const float* __restrict__ x,
    const float* __restrict__ wa, const float* __restrict__ wb,
    const float* __restrict__ rta, const float* __restrict__ rtb,
    const float* __restrict__ rga, const float* __restrict__ rgb,
    float* __restrict__ outI, float* __restrict__ outZ,
    float* __restrict__ outS, float* __restrict__ outL)
{
    extern __shared__ float smem[];
    float* tZ = smem;                               // [32][32][33]
    unsigned* uM = (unsigned*)(smem + 32 * WARP_TILE);  // [32][32]

    const int b = blockIdx.x >> 2;
    const int quarter = blockIdx.x & 3;
    const int tid = threadIdx.x;
    const int w = tid >> 5;            // 0..31
    const int lane = tid & 31;
    const int c = w >> 1;              // channel 0..15
    const int h = w & 1;               // half of the quarter
    const int fidx = c & 7;
    const int isB = c >> 3;

    const float* wrow = (isB ? wb : wa) + fidx * KW;
    const float rt = (isB ? rtb : rta)[fidx];
    const float rg = (isB ? rgb : rga)[0];

    float we[KW];
    float nsq = 0.f;
#pragma unroll
    for (int k = 0; k < KW; k++) { we[k] = wrow[k]; nsq = fmaf(we[k], we[k], nsq); }
    float norm = sqrtf(nsq);
    if (norm < 1e-8f) norm = 1e-8f;
    const float g = softplusf(rg) + 1e-4f;
    const float scale = g * XSC / norm;    // GAIN = 1
#pragma unroll
    for (int k = 0; k < KW; k++) we[k] *= scale;

    const float alpha = expf(-1.0f / (softplusf(rt) + 1e-4f));
    const float oma = 1.0f - alpha;
    const float inv_oma = 1.0f / oma;
    const float invB = 1.0f / BETA;
    const float nBT = -BETA * THRV;

    const float* xr = x + ((size_t)(b * 2 + isB) << 16);
    const int p0 = quarter * 16384 + h * 8192 + lane * 256;
    const int warm = (p0 == 0) ? 0 : 64;
    int lcur = p0 - warm;

    // sliding window: xw[0..7] = x[l-8 .. l-1]
    float xw[12];
    if (lcur >= 8) {
        float4 a4 = *(const float4*)(xr + lcur - 8);
        float4 b4 = *(const float4*)(xr + lcur - 4);
        xw[0] = a4.x; xw[1] = a4.y; xw[2] = a4.z; xw[3] = a4.w;
        xw[4] = b4.x; xw[5] = b4.y; xw[6] = b4.z; xw[7] = b4.w;
    } else {
#pragma unroll
        for (int k = 0; k < 8; k++) xw[k] = 0.f;
    }

    float v = 0.f;

    // ---- warmup (0 or 64 steps), no emission ----
    for (int gg = 0; gg < (warm >> 2); ++gg) {
        float4 xv = *(const float4*)(xr + lcur);
        xw[8] = xv.x; xw[9] = xv.y; xw[10] = xv.z; xw[11] = xv.w;
#pragma unroll
        for (int k = 0; k < 4; k++) {
            float I = 0.f;
#pragma unroll
            for (int j = 0; j < 8; j++) I = fmaf(we[j], xw[k + 1 + j], I);
            float vpre = fmaf(alpha, v, oma * I);
            v = (vpre >= THRV) ? 0.f : vpre;
        }
#pragma unroll
        for (int j = 0; j < 8; j++) xw[j] = xw[j + 4];
        lcur += 4;
    }

    float* mtZ = tZ + w * WARP_TILE;
    float* rowZ = mtZ + lane * TILE_STRIDE;
    const size_t seqoff = ((size_t)(b * NC + c)) << 16;
    const int rsub = lane >> 3;          // 0..3
    const int cq = (lane & 7) * 4;       // 0,4,...,28

    for (int ph = 0; ph < 8; ++ph) {
        rowZ[32] = v;                    // carry: post-reset v at phase entry
        unsigned smask = 0u;
#pragma unroll
        for (int sp = 0; sp < 2; ++sp) {
            float4 xq[4];
#pragma unroll
            for (int gg = 0; gg < 4; gg++) xq[gg] = *(const float4*)(xr + lcur + gg * 4);
#pragma unroll
            for (int gg = 0; gg < 4; gg++) {
                float4 xv = xq[gg];
                xw[8] = xv.x; xw[9] = xv.y; xw[10] = xv.z; xw[11] = xv.w;
#pragma unroll
                for (int k = 0; k < 4; k++) {
                    const int idx = sp * 16 + gg * 4 + k;
                    float I = 0.f;
#pragma unroll
                    for (int j = 0; j < 8; j++) I = fmaf(we[j], xw[k + 1 + j], I);
                    float vpre = fmaf(alpha, v, oma * I);
                    rowZ[idx] = fmaf(BETA, vpre, nBT);
                    bool sp_ = (vpre >= THRV);
                    smask |= (sp_ ? 1u : 0u) << idx;
                    v = sp_ ? 0.f : vpre;
                }
#pragma unroll
                for (int j = 0; j < 8; j++) xw[j] = xw[j + 4];
            }
            lcur += 16;
        }
        uM[w * 32 + lane] = smask;
        __syncwarp();

        // ---- warp-local drain: reconstruct I from z; coalesced float4 stores ----
        const size_t lbase = (size_t)(quarter * 16384 + h * 8192 + ph * 32);
#pragma unroll
        for (int it = 0; it < 8; ++it) {
            const int r = it * 4 + rsub;
            const float* rw = mtZ + r * TILE_STRIDE;
            const unsigned mm = uM[w * 32 + r];
            float z0 = rw[cq], z1 = rw[cq + 1], z2 = rw[cq + 2], z3 = rw[cq + 3];
            float vprev;
            if (cq == 0) {
                vprev = rw[32];                       // carry: already post-reset v
            } else {
                float zp = rw[cq - 1];
                float vp = fmaf(zp, invB, THRV);
                vprev = ((mm >> (cq - 1)) & 1u) ? 0.f : vp;
            }
            float vp0 = fmaf(z0, invB, THRV);
            float vp1 = fmaf(z1, invB, THRV);
            float vp2 = fmaf(z2, invB, THRV);
            float vp3 = fmaf(z3, invB, THRV);
            float s0 = (float)((mm >> cq) & 1u);
            float s1 = (float)((mm >> (cq + 1)) & 1u);
            float s2 = (float)((mm >> (cq + 2)) & 1u);
            float s3 = (float)((mm >> (cq + 3)) & 1u);
            float4 vi;
            vi.x = (vp0 - alpha * vprev) * inv_oma;
            vi.y = (vp1 - alpha * (s0 != 0.f ? 0.f : vp0)) * inv_oma;
            vi.z = (vp2 - alpha * (s1 != 0.f ? 0.f : vp1)) * inv_oma;
            vi.w = (vp3 - alpha * (s2 != 0.f ? 0.f : vp2)) * inv_oma;
            const size_t gi = seqoff + lbase + (size_t)r * 256 + cq;
            __stcs((float4*)(outI + gi), vi);
            __stcs((float4*)(outZ + gi), make_float4(z0, z1, z2, z3));
            __stcs((float4*)(outS + gi), make_float4(s0, s1, s2, s3));
        }
        __syncthreads();

        // ---- fused logits: max over 16 channels, all 1024 threads, float2 ----
        {
            const int hh = tid >> 9;            // 0..1
            const int j  = (tid >> 4) & 31;     // chunk row
            const int q  = (tid & 15) * 2;      // step pair
            const float* p = tZ + hh * WARP_TILE + j * TILE_STRIDE + q;
            float m0 = p[0], m1 = p[1];
#pragma unroll
            for (int c2 = 1; c2 < 16; ++c2) {
                p += 2 * WARP_TILE;
                m0 = fmaxf(m0, p[0]); m1 = fmaxf(m1, p[1]);
            }
            const size_t gl = (((size_t)b) << 16)
                            + (size_t)(quarter * 16384 + hh * 8192 + j * 256 + ph * 32 + q);
            __stcs((float2*)(outL + gl), make_float2(m0, m1));
        }
        __syncthreads();
    }
}

extern "C" void kernel_launch(void* const* d_in, const int* in_sizes, int n_in,
                              void* d_out, int out_size)
{
    const float* x   = (const float*)d_in[0];
    const float* wa  = (const float*)d_in[1];
    const float* wb  = (const float*)d_in[2];
    const float* rta = (const float*)d_in[3];
    const float* rtb = (const float*)d_in[4];
    const float* rga = (const float*)d_in[5];
    const float* rgb = (const float*)d_in[6];

    float* out = (float*)d_out;
    const size_t plane = (size_t)NB * NC * LSEQ;   // 33554432
    float* outI = out;
    float* outZ = out + plane;
    float* outS = out + 2 * plane;
    float* outL = out + 3 * plane;

    cudaFuncSetAttribute(snn_fused, cudaFuncAttributeMaxDynamicSharedMemorySize, SMEM_BYTES);
    snn_fused<<<128, 1024, SMEM_BYTES>>>(x, wa, wb, rta, rtb, rga, rgb,
                                         outI, outZ, outS, outL);
}

// round 6
// speedup vs baseline: 1.3042x; 1.1206x over previous
#include <cuda_runtime.h>

#define LSEQ 65536
#define NB 32
#define NC 16
#define KW 8
#define THRV 0.25f
#define BETA 15.0f
#define XSC 20.0f

#define TILE_STRIDE 33                 // 32 steps + carry slot (col 32)
#define WARP_TILE (32 * TILE_STRIDE)   // per-warp z tile, 1056 floats
#define SMEM_FLOATS (16 * WARP_TILE)   // z tiles only (16 warps)
#define SMEM_BYTES (SMEM_FLOATS * 4)   // 67584 -> 2 blocks/SM

__device__ __forceinline__ float softplusf(float x) {
    return (x > 0.f) ? (x + log1pf(expf(-x))) : log1pf(expf(x));
}

// 256 blocks x 512 threads (16 warps, 2 blocks/SM). block=(b, eighth of L);
// warp w = channel. Lane owns a 256-step chunk at eighth*8192 + lane*256,
// warmed up 48 steps from v=0 (alpha^48~1e-7; spike resets sync exactly).
// 8 phases x 32 steps. Only z is staged in smem. Everything else is derived:
//   s = (z >= 0) ; vpre = z/BETA + THR ; v_prev = (z_prev>=0) ? 0 : vpre_prev
//   I = (vpre - alpha*v_prev) / (1-alpha)
// Carry (post-reset v at phase entry) lives in tile col 32. Logits fused.
__global__ __launch_bounds__(512, 2) void snn_fused(
    const float* __restrict__ x,
    const float* __restrict__ wa, const float* __restrict__ wb,
    const float* __restrict__ rta, const float* __restrict__ rtb,
    const float* __restrict__ rga, const float* __restrict__ rgb,
    float* __restrict__ outI, float* __restrict__ outZ,
    float* __restrict__ outS, float* __restrict__ outL)
{
    extern __shared__ float smem[];
    float* tZ = smem;                               // [16][32][33]

    const int b = blockIdx.x >> 3;
    const int eighth = blockIdx.x & 7;
    const int tid = threadIdx.x;
    const int w = tid >> 5;            // channel 0..15
    const int lane = tid & 31;
    const int fidx = w & 7;
    const int isB = w >> 3;

    const float* wrow = (isB ? wb : wa) + fidx * KW;
    const float rt = (isB ? rtb : rta)[fidx];
    const float rg = (isB ? rgb : rga)[0];

    float wo[KW];
    float nsq = 0.f;
#pragma unroll
    for (int k = 0; k < KW; k++) { wo[k] = wrow[k]; nsq = fmaf(wo[k], wo[k], nsq); }
    float norm = sqrtf(nsq);
    if (norm < 1e-8f) norm = 1e-8f;
    const float g = softplusf(rg) + 1e-4f;

    const float alpha = expf(-1.0f / (softplusf(rt) + 1e-4f));
    const float oma = 1.0f - alpha;
    const float inv_oma = 1.0f / oma;
    const float invB = 1.0f / BETA;
    const float nBT = -BETA * THRV;

    const float scale = g * XSC / norm * oma;   // conv directly produces (1-a)*I
#pragma unroll
    for (int k = 0; k < KW; k++) wo[k] *= scale;

    const float* xr = x + ((size_t)(b * 2 + isB) << 16);
    const int p0 = eighth * 8192 + lane * 256;
    const int warm = (p0 == 0) ? 0 : 48;
    int lcur = p0 - warm;

    // sliding window: xw[0..7] = x[l-8 .. l-1]
    float xw[12];
    if (lcur >= 8) {
        float4 a4 = *(const float4*)(xr + lcur - 8);
        float4 b4 = *(const float4*)(xr + lcur - 4);
        xw[0] = a4.x; xw[1] = a4.y; xw[2] = a4.z; xw[3] = a4.w;
        xw[4] = b4.x; xw[5] = b4.y; xw[6] = b4.z; xw[7] = b4.w;
    } else {
#pragma unroll
        for (int k = 0; k < 8; k++) xw[k] = 0.f;
    }

    // vp = pre-reset membrane of previous step (vp=0 start: acts like v=0)
    float vp = 0.f;

    // ---- warmup (0 or 48 steps), no emission ----
    for (int gg = 0; gg < (warm >> 2); ++gg) {
        float4 xv = *(const float4*)(xr + lcur);
        xw[8] = xv.x; xw[9] = xv.y; xw[10] = xv.z; xw[11] = xv.w;
#pragma unroll
        for (int k = 0; k < 4; k++) {
            float I = 0.f;
#pragma unroll
            for (int j = 0; j < 8; j++) I = fmaf(wo[j], xw[k + 1 + j], I);
            float cand = fmaf(alpha, vp, I);
            vp = (vp >= THRV) ? I : cand;
        }
#pragma unroll
        for (int j = 0; j < 8; j++) xw[j] = xw[j + 4];
        lcur += 4;
    }

    float* mtZ = tZ + w * WARP_TILE;
    float* rowZ = mtZ + lane * TILE_STRIDE;
    const size_t seqoff = ((size_t)(b * NC + w)) << 16;
    const int rsub = lane >> 3;          // 0..3
    const int cq = (lane & 7) * 4;       // 0,4,...,28

    for (int ph = 0; ph < 8; ++ph) {
        rowZ[32] = (vp >= THRV) ? 0.f : vp;   // carry: post-reset v at phase entry
#pragma unroll
        for (int sp = 0; sp < 2; ++sp) {
            float4 xq[4];
#pragma unroll
            for (int gg = 0; gg < 4; gg++) xq[gg] = *(const float4*)(xr + lcur + gg * 4);
#pragma unroll
            for (int gg = 0; gg < 4; gg++) {
                float4 xv = xq[gg];
                xw[8] = xv.x; xw[9] = xv.y; xw[10] = xv.z; xw[11] = xv.w;
#pragma unroll
                for (int k = 0; k < 4; k++) {
                    const int idx = sp * 16 + gg * 4 + k;
                    float I = 0.f;
#pragma unroll
                    for (int j = 0; j < 8; j++) I = fmaf(wo[j], xw[k + 1 + j], I);
                    float cand = fmaf(alpha, vp, I);
                    vp = (vp >= THRV) ? I : cand;       // vp = vpre_t
                    rowZ[idx] = fmaf(BETA, vp, nBT);    // z_t (sign == spike)
                }
#pragma unroll
                for (int j = 0; j < 8; j++) xw[j] = xw[j + 4];
            }
            lcur += 16;
        }
        __syncthreads();

        // ---- warp-local drain: I,z,s from z tile; coalesced float4 stores ----
        const size_t lbase = (size_t)(eighth * 8192 + ph * 32);
#pragma unroll
        for (int it = 0; it < 8; ++it) {
            const int r = it * 4 + rsub;
            const float* rw = mtZ + r * TILE_STRIDE;
            float z0 = rw[cq], z1 = rw[cq + 1], z2 = rw[cq + 2], z3 = rw[cq + 3];
            float vprev;
            if (cq == 0) {
                vprev = rw[32];                       // carry: already post-reset
            } else {
                float zp = rw[cq - 1];
                vprev = (zp >= 0.f) ? 0.f : fmaf(zp, invB, THRV);
            }
            float vp0 = fmaf(z0, invB, THRV);
            float vp1 = fmaf(z1, invB, THRV);
            float vp2 = fmaf(z2, invB, THRV);
            float vp3 = fmaf(z3, invB, THRV);
            float4 vs;
            vs.x = (z0 >= 0.f) ? 1.f : 0.f;
            vs.y = (z1 >= 0.f) ? 1.f : 0.f;
            vs.z = (z2 >= 0.f) ? 1.f : 0.f;
            vs.w = (z3 >= 0.f) ? 1.f : 0.f;
            float4 vi;
            vi.x = (vp0 - alpha * vprev) * inv_oma;
            vi.y = (vp1 - alpha * ((z0 >= 0.f) ? 0.f : vp0)) * inv_oma;
            vi.z = (vp2 - alpha * ((z1 >= 0.f) ? 0.f : vp1)) * inv_oma;
            vi.w = (vp3 - alpha * ((z2 >= 0.f) ? 0.f : vp2)) * inv_oma;
            const size_t gi = seqoff + lbase + (size_t)r * 256 + cq;
            __stcs((float4*)(outI + gi), vi);
            __stcs((float4*)(outZ + gi), make_float4(z0, z1, z2, z3));
            __stcs((float4*)(outS + gi), vs);
        }

        // ---- fused logits: max over 16 channels, 512 threads, float2 out ----
        {
            const int j = tid >> 4;             // chunk row 0..31
            const int q = (tid & 15) * 2;       // step pair
            const float* p = tZ + j * TILE_STRIDE + q;
            float m0 = p[0], m1 = p[1];
#pragma unroll
            for (int c2 = 1; c2 < 16; ++c2) {
                p += WARP_TILE;
                m0 = fmaxf(m0, p[0]); m1 = fmaxf(m1, p[1]);
            }
            const size_t gl = (((size_t)b) << 16)
                            + (size_t)(eighth * 8192 + j * 256 + ph * 32 + q);
            __stcs((float2*)(outL + gl), make_float2(m0, m1));
        }
        __syncthreads();
    }
}

extern "C" void kernel_launch(void* const* d_in, const int* in_sizes, int n_in,
                              void* d_out, int out_size)
{
    const float* x   = (const float*)d_in[0];
    const float* wa  = (const float*)d_in[1];
    const float* wb  = (const float*)d_in[2];
    const float* rta = (const float*)d_in[3];
    const float* rtb = (const float*)d_in[4];
    const float* rga = (const float*)d_in[5];
    const float* rgb = (const float*)d_in[6];

    float* out = (float*)d_out;
    const size_t plane = (size_t)NB * NC * LSEQ;   // 33554432
    float* outI = out;
    float* outZ = out + plane;
    float* outS = out + 2 * plane;
    float* outL = out + 3 * plane;

    cudaFuncSetAttribute(snn_fused, cudaFuncAttributeMaxDynamicSharedMemorySize, SMEM_BYTES);
    snn_fused<<<256, 512, SMEM_BYTES>>>(x, wa, wb, rta, rtb, rga, rgb,
                                        outI, outZ, outS, outL);
}